// round 15
// baseline (speedup 1.0000x reference)
#include <cuda_runtime.h>

#define BB 8
#define DD 16
#define HH 384
#define WW 384
#define HW (HH * WW)            /* 147456 */
#define NBV (DD * HW)           /* 2359296 */
#define NT (BB * NBV)           /* 18874368 voxels */
#define NW (NT / 32)            /* 589824 bit-words */
#define ROWS (BB * DD * HH)     /* 49152 rows of W=384 */
#define WPR 12                  /* words per row */
#define SLOTS 192               /* max runs per row */
#define NR (ROWS * SLOTS)       /* 9437184 run slots (< 2^24) */

#define STRONGBIT (1 << 24)     /* set on keys of runs WITHOUT strong voxels */
#define IDXMASK (STRONGBIT - 1)

// ---- scratch (__device__ globals; no runtime allocation) ----
__device__ int g_parent[NR];          // stores KEYS (index | maybe STRONGBIT)
__device__ int g_cnt[NR];
__device__ unsigned g_weak[NW];
__device__ unsigned g_strong[NW];
__device__ unsigned g_hyst[NW];
__device__ unsigned g_mask2[NW];
__device__ unsigned char g_pref[NW];  // run starts in row before this word

// findRoot with path halving; returns the ROOT KEY.
// A node idx is root iff P[idx] == key(idx); keys are unique per index, so
// P[k & IDXMASK] == k  <=>  k is a root key. Halving stores are ancestor keys
// (monotone toward root) — benign races only.
__device__ __forceinline__ int findRoot(int* P, int i) {
    int k = P[i];
    int ki = k & IDXMASK;
    int kk = P[ki];
    while (k != kk) {
        P[i] = kk;          // path halving
        i = ki;
        k = kk;
        ki = k & IDXMASK;
        kk = P[ki];
    }
    return k;
}

__device__ __forceinline__ void unite(int* P, int ai, int bi) {
    int ak = findRoot(P, ai);
    int bk = findRoot(P, bi);
    while (ak != bk) {
        if (ak > bk) { int t = ak; ak = bk; bk = t; }
        int bidx = bk & IDXMASK;
        int old = atomicMin(&P[bidx], ak);
        if (old == bk) return;            // bidx was still a root; linked
        bk = findRoot(P, old & IDXMASK);  // lost race; chase new parent
    }
}

__device__ __forceinline__ unsigned lemask(int b) { return (2u << b) - 1u; }

// K1 (warp/row): thresholds -> masks, run prefix, keyed parent init
// (weak-only key = ri|STRONGBIT), then clear STRONGBIT for strong-bearing runs.
__global__ void k1_threshold(const float* __restrict__ in) {
    int t = blockIdx.x * blockDim.x + threadIdx.x;
    int row = t >> 5, lane = t & 31;
    if (row >= ROWS) return;
    int base = row * WW, wb = row * WPR, rbase = row * SLOTS;
    unsigned myW = 0, myS = 0;
#pragma unroll
    for (int wd = 0; wd < WPR; wd++) {
        float v = in[base + wd * 32 + lane];
        unsigned ww = __ballot_sync(0xffffffffu, v >= 0.8f);
        unsigned ss = __ballot_sync(0xffffffffu, v >= 0.92f);
        if (lane == wd) { myW = ww; myS = ss; }
    }
    unsigned prevW = __shfl_up_sync(0xffffffffu, myW, 1);
    unsigned prevS = __shfl_up_sync(0xffffffffu, myS, 1);
    if (lane == 0) { prevW = 0; prevS = 0; }
    unsigned sC = myW & ~((myW << 1) | (prevW >> 31));
    int cnt = __popc(sC);
    int x = cnt;
#pragma unroll
    for (int o = 1; o < 32; o <<= 1) {
        int y = __shfl_up_sync(0xffffffffu, x, o);
        if (lane >= o) x += y;
    }
    int pC = x - cnt;
    if (lane < WPR) {
        g_weak[wb + lane] = myW;
        g_strong[wb + lane] = myS;
        g_pref[wb + lane] = (unsigned char)pC;
    }
    int nruns = __shfl_sync(0xffffffffu, x, 31);
    int initSlots = (nruns + 31) & ~31;
    for (int o = lane; o < initSlots; o += 32)
        g_parent[rbase + o] = (rbase + o) | STRONGBIT;   // default: no strong
    __syncwarp();
    // clear STRONGBIT on runs containing strong segments (strong ⊆ weak)
    if (lane < WPR && myS) {
        unsigned sS = myS & ~((myS << 1) | (prevS >> 31));
        while (sS) {
            int b = __ffs(sS) - 1; sS &= sS - 1;
            int ri = rbase + pC + __popc(sC & lemask(b)) - 1;
            g_parent[ri] = ri;                            // key without STRONGBIT
        }
    }
}

// K2/K5b (thread/word): one unite per overlap segment with h-1 / z-1 rows
template <bool SECOND>
__global__ void k2_merge() {
    int wi = blockIdx.x * blockDim.x + threadIdx.x;
    if (wi >= NW) return;
    int row = wi / WPR, wd = wi - row * WPR;
    const unsigned* __restrict__ M = SECOND ? g_mask2 : g_weak;
    unsigned cur = M[wi];
    if (!cur) return;
    int h = row % HH, z = (row / HH) % DD;
    bool hasH = (h > 0), hasD = (z > 0);
    if (!hasH && !hasD) return;
    unsigned prevC = wd ? M[wi - 1] : 0;
    unsigned sC = cur & ~((cur << 1) | (prevC >> 31));
    int pC = g_pref[wi];
    int rbase = row * SLOTS;
    if (hasH) {
        unsigned nh = M[wi - WPR];
        unsigned ov = cur & nh;
        if (ov) {
            unsigned prevH = wd ? M[wi - 1 - WPR] : 0;
            unsigned sH = nh & ~((nh << 1) | (prevH >> 31));
            unsigned so = ov & ~((ov << 1) | ((prevC & prevH) >> 31));
            int pH = g_pref[wi - WPR];
            int nb = (row - 1) * SLOTS;
            while (so) {
                int b = __ffs(so) - 1; so &= so - 1;
                int ra = rbase + pC + __popc(sC & lemask(b)) - 1;
                int rb = nb + pH + __popc(sH & lemask(b)) - 1;
                unite(g_parent, ra, rb);
            }
        }
    }
    if (hasD) {
        unsigned nd = M[wi - WPR * HH];
        unsigned ov = cur & nd;
        if (ov) {
            unsigned prevD = wd ? M[wi - 1 - WPR * HH] : 0;
            unsigned sD = nd & ~((nd << 1) | (prevD >> 31));
            unsigned so = ov & ~((ov << 1) | ((prevC & prevD) >> 31));
            int pD = g_pref[wi - WPR * HH];
            int nb = (row - HH) * SLOTS;
            while (so) {
                int b = __ffs(so) - 1; so &= so - 1;
                int ra = rbase + pC + __popc(sC & lemask(b)) - 1;
                int rb = nb + pD + __popc(sD & lemask(b)) - 1;
                unite(g_parent, ra, rb);
            }
        }
    }
}

// K4 (thread/word): hysteresis — kept iff root key lacks STRONGBIT
__global__ void k4_hyst() {
    int wi = blockIdx.x * blockDim.x + threadIdx.x;
    if (wi >= NW) return;
    unsigned cur = g_weak[wi];
    unsigned hy = 0;
    if (cur) {
        int row = wi / WPR, wd = wi - row * WPR;
        unsigned prevC = wd ? g_weak[wi - 1] : 0;
        unsigned sC = cur & ~((cur << 1) | (prevC >> 31));
        int pC = g_pref[wi];
        int rbase = row * SLOTS;
        unsigned m = cur;
        while (m) {
            int b = __ffs(m) - 1;
            unsigned x = m >> b;
            int len = (x == 0xffffffffu) ? 32 : (__ffs(~x) - 1);
            unsigned seg = ((len == 32) ? 0xffffffffu : ((1u << len) - 1u)) << b;
            int ri = rbase + pC + __popc(sC & lemask(b)) - 1;
            int rk = findRoot(g_parent, ri);
            if (!(rk & STRONGBIT)) hy |= seg;
            m &= ~seg;
        }
    }
    g_hyst[wi] = hy;
}

// K5a (warp/row): z-closing (lane-parallel loads) + prefix + PARTIAL init
__global__ void k5a_close() {
    int t = blockIdx.x * blockDim.x + threadIdx.x;
    int row = t >> 5, lane = t & 31;
    if (row >= ROWS) return;
    int z = (row / HH) % DD;
    int wb = row * WPR, rbase = row * SLOTS;
    const int ZOFF = WPR * HH;
    unsigned my2 = 0;
    if (lane < WPR) {
        int wi = wb + lane;
        unsigned h0  = g_hyst[wi];
        unsigned hm1 = (z >= 1)      ? g_hyst[wi - ZOFF]     : 0u;
        unsigned hm2 = (z >= 2)      ? g_hyst[wi - 2 * ZOFF] : 0u;
        unsigned hp1 = (z <= DD - 2) ? g_hyst[wi + ZOFF]     : 0u;
        unsigned hp2 = (z <= DD - 3) ? g_hyst[wi + 2 * ZOFF] : 0u;
        unsigned dilm = hm2 | hm1 | h0;
        unsigned dil0 = hm1 | h0 | hp1;
        unsigned dilp = h0 | hp1 | hp2;
        my2 = (z ? dilm : 0xffffffffu) & dil0 &
              ((z < DD - 1) ? dilp : 0xffffffffu);
    }
    unsigned prev = __shfl_up_sync(0xffffffffu, my2, 1);
    if (lane == 0) prev = 0;
    unsigned sC = my2 & ~((my2 << 1) | (prev >> 31));
    int cnt = __popc(sC);
    int x = cnt;
#pragma unroll
    for (int o = 1; o < 32; o <<= 1) {
        int y = __shfl_up_sync(0xffffffffu, x, o);
        if (lane >= o) x += y;
    }
    if (lane < WPR) {
        g_mask2[wb + lane] = my2;
        g_pref[wb + lane] = (unsigned char)(x - cnt);
    }
    int nruns = __shfl_sync(0xffffffffu, x, 31);
    int initSlots = (nruns + 31) & ~31;
    for (int o = lane; o < initSlots; o += 32) {
        int ri = rbase + o;
        g_parent[ri] = ri;      // pass-2 keys = plain indices
        g_cnt[ri] = 0;
    }
}

// K5c (thread/word): flatten run starts + per-word-piece length at root
__global__ void k5c_flatten_count() {
    int wi = blockIdx.x * blockDim.x + threadIdx.x;
    if (wi >= NW) return;
    unsigned cur = g_mask2[wi];
    if (!cur) return;
    int row = wi / WPR, wd = wi - row * WPR;
    unsigned prevC = wd ? g_mask2[wi - 1] : 0;
    unsigned sC = cur & ~((cur << 1) | (prevC >> 31));
    int pC = g_pref[wi];
    int rbase = row * SLOTS;
    unsigned m = cur;
    while (m) {
        int b = __ffs(m) - 1;
        unsigned x = m >> b;
        int len = (x == 0xffffffffu) ? 32 : (__ffs(~x) - 1);
        unsigned seg = ((len == 32) ? 0xffffffffu : ((1u << len) - 1u)) << b;
        int ri = rbase + pC + __popc(sC & lemask(b)) - 1;
        int rk = findRoot(g_parent, ri);
        int ridx = rk & IDXMASK;
        if (((sC >> b) & 1) && ridx != ri) g_parent[ri] = rk;
        atomicAdd(&g_cnt[ridx], len);
        m &= ~seg;
    }
}

// K6 (thread/word): keep mask per word, float4 stores
__global__ void k6_final(float* __restrict__ out) {
    int wi = blockIdx.x * blockDim.x + threadIdx.x;
    if (wi >= NW) return;
    unsigned cur = g_mask2[wi];
    unsigned keep = 0;
    if (cur) {
        int row = wi / WPR, wd = wi - row * WPR;
        unsigned prevC = wd ? g_mask2[wi - 1] : 0;
        unsigned sC = cur & ~((cur << 1) | (prevC >> 31));
        int pC = g_pref[wi];
        int rbase = row * SLOTS;
        unsigned m = cur;
        while (m) {
            int b = __ffs(m) - 1;
            unsigned x = m >> b;
            int len = (x == 0xffffffffu) ? 32 : (__ffs(~x) - 1);
            unsigned seg = ((len == 32) ? 0xffffffffu : ((1u << len) - 1u)) << b;
            int ri = rbase + pC + __popc(sC & lemask(b)) - 1;
            int rk = findRoot(g_parent, ri);
            if (g_cnt[rk & IDXMASK] >= 20) keep |= seg;
            m &= ~seg;
        }
    }
    float4* out4 = reinterpret_cast<float4*>(out) + wi * 8;
#pragma unroll
    for (int k = 0; k < 8; k++) {
        out4[k] = make_float4(
            ((keep >> (4 * k + 0)) & 1) ? 1.0f : 0.0f,
            ((keep >> (4 * k + 1)) & 1) ? 1.0f : 0.0f,
            ((keep >> (4 * k + 2)) & 1) ? 1.0f : 0.0f,
            ((keep >> (4 * k + 3)) & 1) ? 1.0f : 0.0f);
    }
}

extern "C" void kernel_launch(void* const* d_in, const int* in_sizes, int n_in,
                              void* d_out, int out_size) {
    const float* in = (const float*)d_in[0];
    float* out = (float*)d_out;

    const int TPB = 256;
    const int GRID_ROW = (ROWS * 32) / TPB;     // 6144 (warp per row)
    const int GRID_W   = (NW + TPB - 1) / TPB;  // 2304 (thread per word)

    k1_threshold<<<GRID_ROW, TPB>>>(in);
    k2_merge<false><<<GRID_W, TPB>>>();
    k4_hyst<<<GRID_W, TPB>>>();
    k5a_close<<<GRID_ROW, TPB>>>();
    k2_merge<true><<<GRID_W, TPB>>>();
    k5c_flatten_count<<<GRID_W, TPB>>>();
    k6_final<<<GRID_W, TPB>>>(out);
}